// round 2
// baseline (speedup 1.0000x reference)
#include <cuda_runtime.h>
#include <math.h>

#define BGR 256      // batch graphs
#define LNO 64       // nodes per graph
#define NND 16384    // total nodes
#define NED 65536    // total edges
#define NH  8        // heads
#define DIN 512      // d_inner
#define HDIM 64      // d per head

// ---- static scratch (no dynamic allocation allowed) ----
__device__ float g_A[(size_t)BGR * NH * LNO * LNO];  // 33.5 MB; reused for M
__device__ float g_CB[(size_t)BGR * LNO * LNO];      // 4 MB
__device__ float g_dts[NH * NND];
__device__ float g_dtt[NH * NND];
__device__ float g_dnorm[NH * NND];
__device__ float g_ec[NND];

__device__ __forceinline__ float softplusf(float x) {
    // matches jax.nn.softplus = max(x,0) + log1p(exp(-|x|))
    return fmaxf(x, 0.f) + log1pf(expf(-fabsf(x)));
}

// ---- zero accumulators ----
__global__ void k_zero() {
    int idx = blockIdx.x * blockDim.x + threadIdx.x;
    int stride = gridDim.x * blockDim.x;
    for (size_t i = idx; i < (size_t)BGR * NH * LNO * LNO; i += stride) g_A[i] = 0.f;
    for (int i = idx; i < NH * NND; i += stride) g_dnorm[i] = 0.f;
    for (int i = idx; i < NND; i += stride) g_ec[i] = 0.f;
}

// ---- per-node dt softplus: dt_s[j,i], dt_t[j,i] ----
__global__ void k_node(const float* __restrict__ dt, const float* __restrict__ bias) {
    int i = blockIdx.x * blockDim.x + threadIdx.x;
    if (i >= NND) return;
    #pragma unroll
    for (int j = 0; j < NH; j++) {
        float b = __ldg(&bias[j]);
        g_dts[j * NND + i] = softplusf(dt[i * 16 + 2 * j] + b);
        g_dtt[j * NND + i] = softplusf(dt[i * 16 + 2 * j + 1] + b);
    }
}

// ---- edge scatter: A, dnorm, ec ----
__global__ void k_edge(const float* __restrict__ dte_in, const float* __restrict__ bias,
                       const float* __restrict__ mask, const int* __restrict__ eidx) {
    int e = blockIdx.x * blockDim.x + threadIdx.x;
    if (e >= NED) return;
    int s = eidx[e];
    int d = eidx[NED + e];
    int batch = s / LNO;
    int sl = s % LNO, dl = d % LNO;
    float m = mask[e];
    atomicAdd(&g_ec[d], m);
    const float inv3 = 0.57735026918962576f;  // 1/sqrt(3)
    #pragma unroll
    for (int j = 0; j < NH; j++) {
        float te = softplusf(dte_in[e * NH + j] + __ldg(&bias[j]));
        float sum = (g_dts[j * NND + s] + g_dtt[j * NND + d] + te) * inv3;
        float ex = expf(-sum) * m;
        sum *= m;
        atomicAdd(&g_dnorm[j * NND + d], sum);
        atomicAdd(&g_A[(((size_t)batch * NH + j) * LNO + dl) * LNO + sl], ex);
    }
}

// ---- CB[b,i,t] = dot(C[b,i,:], B[b,t,:]) over 512 ----
__global__ void __launch_bounds__(256) k_cb(const float* __restrict__ Cin,
                                            const float* __restrict__ Bin) {
    __shared__ float Cs[LNO][LNO + 1];
    __shared__ float Bs[LNO][LNO + 1];
    int batch = blockIdx.x;
    int tid = threadIdx.x;
    int rt = tid >> 4, ct = tid & 15;
    float acc[4][4] = {};
    const float* Cbase = Cin + (size_t)batch * LNO * DIN;
    const float* Bbase = Bin + (size_t)batch * LNO * DIN;
    for (int d0 = 0; d0 < DIN; d0 += LNO) {
        for (int idx = tid; idx < LNO * LNO; idx += 256) {
            int r = idx >> 6, c = idx & 63;
            Cs[r][c] = Cbase[r * DIN + d0 + c];
            Bs[r][c] = Bbase[r * DIN + d0 + c];
        }
        __syncthreads();
        #pragma unroll 8
        for (int k = 0; k < LNO; k++) {
            float cv[4], bv[4];
            #pragma unroll
            for (int r = 0; r < 4; r++) cv[r] = Cs[rt * 4 + r][k];
            #pragma unroll
            for (int c = 0; c < 4; c++) bv[c] = Bs[ct * 4 + c][k];
            #pragma unroll
            for (int r = 0; r < 4; r++)
                #pragma unroll
                for (int c = 0; c < 4; c++) acc[r][c] += cv[r] * bv[c];
        }
        __syncthreads();
    }
    float* outp = g_CB + (size_t)batch * LNO * LNO;
    #pragma unroll
    for (int r = 0; r < 4; r++)
        #pragma unroll
        for (int c = 0; c < 4; c++)
            outp[(rt * 4 + r) * LNO + ct * 4 + c] = acc[r][c];
}

// ---- per (batch,head): normalize A, forward-substitute L=(I-A)^-1,
//      apply dnorm row-scale and CB Hadamard; write M back over g_A ----
__global__ void __launch_bounds__(64) k_inv() {
    __shared__ float As[LNO][LNO + 1];
    __shared__ float ecs[LNO];
    __shared__ float dns[LNO];
    int blk = blockIdx.x;
    int batch = blk >> 3, head = blk & 7;
    int t = threadIdx.x;
    ecs[t] = g_ec[batch * LNO + t];
    dns[t] = g_dnorm[head * NND + batch * LNO + t];
    __syncthreads();
    float ect = ecs[t];
    float* Ab = g_A + (size_t)blk * LNO * LNO;
    #pragma unroll 4
    for (int i = 0; i < LNO; i++) {
        float p = ecs[i] * ect;
        float sc = (p >= 1.f) ? rsqrtf(p) : 1.f;
        As[i][t] = Ab[i * LNO + t] * sc;
    }
    __syncthreads();
    // forward substitution: each thread owns column t of L entirely in registers.
    float l[LNO];
    #pragma unroll
    for (int i = 0; i < LNO; i++) {
        float acc = (i == t) ? 1.f : 0.f;
        #pragma unroll
        for (int k = 0; k < i; k++) acc += As[i][k] * l[k];
        l[i] = acc;
    }
    const float* CBb = g_CB + (size_t)batch * LNO * LNO;
    #pragma unroll 4
    for (int i = 0; i < LNO; i++) {
        Ab[i * LNO + t] = l[i] * dns[i] * CBb[i * LNO + t];
    }
}

// ---- y[b,head,i,:] = M[b,head] @ x4[b,head] + x*D ----
__global__ void __launch_bounds__(256) k_y(const float* __restrict__ x,
                                           const float* __restrict__ Dv,
                                           float* __restrict__ outp) {
    __shared__ float Ms[LNO][LNO + 1];
    __shared__ float Xs[LNO][LNO + 1];
    int blk = blockIdx.x;
    int batch = blk >> 3, head = blk & 7;
    int tid = threadIdx.x;
    const float* Mb = g_A + (size_t)blk * LNO * LNO;
    const float* xb = x + (size_t)batch * LNO * DIN + head * HDIM;
    for (int idx = tid; idx < LNO * LNO; idx += 256) {
        int r = idx >> 6, c = idx & 63;
        Ms[r][c] = Mb[idx];
        Xs[r][c] = xb[r * DIN + c];
    }
    __syncthreads();
    int rt = tid >> 4, ct = tid & 15;
    float acc[4][4] = {};
    #pragma unroll 8
    for (int k = 0; k < LNO; k++) {
        float mv[4], xv[4];
        #pragma unroll
        for (int r = 0; r < 4; r++) mv[r] = Ms[rt * 4 + r][k];
        #pragma unroll
        for (int c = 0; c < 4; c++) xv[c] = Xs[k][ct * 4 + c];
        #pragma unroll
        for (int r = 0; r < 4; r++)
            #pragma unroll
            for (int c = 0; c < 4; c++) acc[r][c] += mv[r] * xv[c];
    }
    float dv = __ldg(&Dv[head]);
    float* ob = outp + (size_t)batch * LNO * DIN + head * HDIM;
    #pragma unroll
    for (int r = 0; r < 4; r++) {
        int i = rt * 4 + r;
        float4 v;
        v.x = acc[r][0] + Xs[i][ct * 4 + 0] * dv;
        v.y = acc[r][1] + Xs[i][ct * 4 + 1] * dv;
        v.z = acc[r][2] + Xs[i][ct * 4 + 2] * dv;
        v.w = acc[r][3] + Xs[i][ct * 4 + 3] * dv;
        *reinterpret_cast<float4*>(&ob[i * DIN + ct * 4]) = v;
    }
}

extern "C" void kernel_launch(void* const* d_in, const int* in_sizes, int n_in,
                              void* d_out, int out_size) {
    const float* x       = (const float*)d_in[0];
    const float* Bm      = (const float*)d_in[1];
    const float* Cm      = (const float*)d_in[2];
    const float* dt      = (const float*)d_in[3];
    const float* dt_edge = (const float*)d_in[4];
    const float* dt_bias = (const float*)d_in[5];
    const float* Dv      = (const float*)d_in[6];
    const float* masks   = (const float*)d_in[7];
    const int*   eidx    = (const int*)d_in[8];
    // d_in[9] = data_batch, d_in[10] = diameter (fixed 64; A is nilpotent so
    // forward substitution equals the repeated-squaring Neumann sum exactly)
    float* outp = (float*)d_out;

    k_zero<<<512, 256>>>();
    k_node<<<(NND + 255) / 256, 256>>>(dt, dt_bias);
    k_edge<<<(NED + 255) / 256, 256>>>(dt_edge, dt_bias, masks, eidx);
    k_cb<<<BGR, 256>>>(Cm, Bm);
    k_inv<<<BGR * NH, 64>>>();
    k_y<<<BGR * NH, 256>>>(x, Dv, outp);
}

// round 5
// speedup vs baseline: 1.3086x; 1.3086x over previous
#include <cuda_runtime.h>
#include <math.h>

#define BGR 256      // batch graphs
#define LNO 64       // nodes per graph
#define NND 16384    // total nodes
#define NED 65536    // total edges
#define EPG 256      // edges per graph (NED/BGR)
#define NH  8        // heads
#define DIN 512      // d_inner
#define HDIM 64      // d per head

// only global scratch: CB matrices (4 MB)
__device__ float g_CB[(size_t)BGR * LNO * LNO];

__device__ __forceinline__ float softplusf(float x) {
    return fmaxf(x, 0.f) + log1pf(expf(-fabsf(x)));
}

// ---- zero g_CB: 1024 blocks x 256 threads x 1 float4 = 1,048,576 floats ----
__global__ void k_zero_cb() {
    int i = blockIdx.x * blockDim.x + threadIdx.x;
    reinterpret_cast<float4*>(g_CB)[i] = make_float4(0.f, 0.f, 0.f, 0.f);
}

// ---- CB[b,i,t] = dot(C[b,i,:], B[b,t,:]); split-K over 4 slices of 128 ----
__global__ void __launch_bounds__(256) k_cb(const float* __restrict__ Cin,
                                            const float* __restrict__ Bin) {
    __shared__ __align__(16) float Cs[LNO][LNO + 1];
    __shared__ __align__(16) float Bs[LNO][LNO + 1];
    int batch = blockIdx.x >> 2;
    int slice = blockIdx.x & 3;
    int tid = threadIdx.x;
    int rt = tid >> 4, ct = tid & 15;
    const float* Cb = Cin + (size_t)batch * LNO * DIN;
    const float* Bb = Bin + (size_t)batch * LNO * DIN;
    float acc[4][4] = {};
    int dbeg = slice * 128;
    for (int d0 = dbeg; d0 < dbeg + 128; d0 += 64) {
        for (int idx = tid; idx < 1024; idx += 256) {
            int row = idx >> 4, seg = idx & 15;
            float4 cv = *reinterpret_cast<const float4*>(Cb + row * DIN + d0 + seg * 4);
            float4 bv = *reinterpret_cast<const float4*>(Bb + row * DIN + d0 + seg * 4);
            Cs[row][seg * 4 + 0] = cv.x; Cs[row][seg * 4 + 1] = cv.y;
            Cs[row][seg * 4 + 2] = cv.z; Cs[row][seg * 4 + 3] = cv.w;
            Bs[row][seg * 4 + 0] = bv.x; Bs[row][seg * 4 + 1] = bv.y;
            Bs[row][seg * 4 + 2] = bv.z; Bs[row][seg * 4 + 3] = bv.w;
        }
        __syncthreads();
        #pragma unroll 16
        for (int k = 0; k < LNO; k++) {
            float cv[4], bv[4];
            #pragma unroll
            for (int r = 0; r < 4; r++) cv[r] = Cs[rt * 4 + r][k];
            #pragma unroll
            for (int c = 0; c < 4; c++) bv[c] = Bs[ct * 4 + c][k];
            #pragma unroll
            for (int r = 0; r < 4; r++)
                #pragma unroll
                for (int c = 0; c < 4; c++) acc[r][c] += cv[r] * bv[c];
        }
        __syncthreads();
    }
    float* o = g_CB + (size_t)batch * LNO * LNO;
    #pragma unroll
    for (int r = 0; r < 4; r++)
        #pragma unroll
        for (int c = 0; c < 4; c++)
            atomicAdd(&o[(rt * 4 + r) * LNO + ct * 4 + c], acc[r][c]);
}

// ---- fused per-(batch,head): edge scatter (smem) -> normalize ->
//      forward substitution L=(I-A)^-1 -> W = L .* CB -> y = dn*(W@x4) + D*x4 ----
__global__ void __launch_bounds__(256) k_fused(
    const float* __restrict__ x, const float* __restrict__ dt,
    const float* __restrict__ dt_edge, const float* __restrict__ bias,
    const float* __restrict__ Dv, const float* __restrict__ mask,
    const int* __restrict__ eidx, float* __restrict__ outp)
{
    __shared__ __align__(16) float As[LNO * LNO];       // A, later reused as Xs[t][h]
    __shared__ __align__(16) float Ls[LNO * (LNO + 1)]; // L columns, later W
    __shared__ float Apad[LNO];                         // spill row for padded A indexing
    __shared__ float sec[LNO], sdn[LNO], sdts[LNO], sdtt[LNO];

    int blk = blockIdx.x;
    int batch = blk >> 3, head = blk & 7;
    int tid = threadIdx.x;

    // A stored padded stride 65 across As+Apad?  Simpler: keep A in Ls (stride 65)
    // and L in As?  No — use: A lives in Ls[i*65+t] first; after sub, L lives in
    // registers? Keep design: A in Ls is wrong since L overwrites.  Use:
    //   phase1: A in "Ls" buffer (stride 65, conflict-free)
    //   phase2: L written into As (stride 65 doesn't fit 4096... )
    // -> cleanest: A in Ls[65-stride]; L columns built in As[65-...]
    // As is 4096 floats; need 4160 for stride 65 -> use Apad as overflow is messy.
    // Instead: A in Ls (4160 ok), L in As with stride 64 BUT bank-conflict-free
    // because sub reads L only via own column t (addr k*64+t -> distinct banks)
    // and GEMM reads W rows scalar-broadcast (2 addrs/warp, same bank -> 2-way, ok).
    (void)Apad;

    // ---- zero A (in Ls), counters; node softplus ----
    for (int i = tid; i < LNO * (LNO + 1); i += 256) Ls[i] = 0.f;
    if (tid < LNO) {
        sec[tid] = 0.f; sdn[tid] = 0.f;
        float b = __ldg(&bias[head]);
        int node = batch * LNO + tid;
        sdts[tid] = softplusf(dt[node * 16 + 2 * head] + b);
        sdtt[tid] = softplusf(dt[node * 16 + 2 * head + 1] + b);
    }
    __syncthreads();

    // ---- edge scatter: one edge per thread ----
    {
        int e = batch * EPG + tid;
        int s = eidx[e];
        int d = eidx[NED + e];
        int sl = s & 63, dl = d & 63;
        float m = mask[e];
        float te = softplusf(dt_edge[e * NH + head] + __ldg(&bias[head]));
        float sum = (sdts[sl] + sdtt[dl] + te) * 0.57735026918962576f;
        float ex = expf(-sum) * m;
        atomicAdd(&Ls[dl * 65 + sl], ex);       // A[dl][sl]
        atomicAdd(&sdn[dl], sum * m);
        atomicAdd(&sec[dl], m);
    }
    __syncthreads();

    // ---- normalize A by sqrt(max(1, ec_i*ec_t)) ----
    for (int idx = tid; idx < LNO * LNO; idx += 256) {
        int i = idx >> 6, t = idx & 63;
        float p = sec[i] * sec[t];
        float sc = (p >= 1.f) ? rsqrtf(p) : 1.f;
        Ls[i * 65 + t] *= sc;
    }
    __syncthreads();

    // ---- forward substitution: thread t owns column t of L (strictly lower A,
    //      dst>src always).  L stored in As[i*64+t]. No cross-thread deps. ----
    if (tid < LNO) {
        int t = tid;
        for (int i = 0; i < LNO; i++) {
            float acc = (i == t) ? 1.f : 0.f;
            #pragma unroll 4
            for (int k = 0; k < i; k++)
                acc += Ls[i * 65 + k] * As[k * LNO + t];
            As[i * LNO + t] = acc;
        }
    }
    __syncthreads();

    // ---- W = L .* CB   (write into Ls, stride 65);  A in Ls is dead now:
    //      read L from As, CB from global, store W into Ls ----
    const float* CBb = g_CB + (size_t)batch * LNO * LNO;
    for (int idx = tid; idx < LNO * LNO; idx += 256) {
        int i = idx >> 6, t = idx & 63;
        Ls[i * 65 + t] = As[idx] * CBb[idx];
    }
    __syncthreads();

    // ---- load Xs[t][h] into As (L dead now) ----
    const float* xb = x + (size_t)batch * LNO * DIN + head * HDIM;
    for (int idx = tid; idx < 1024; idx += 256) {
        int trow = idx >> 4, c4 = idx & 15;
        float4 v = *reinterpret_cast<const float4*>(xb + trow * DIN + c4 * 4);
        *reinterpret_cast<float4*>(&As[trow * LNO + c4 * 4]) = v;
    }
    __syncthreads();

    // ---- y[i][h] = dn[i] * sum_k W[i][k]*Xs[k][h]  + D*Xs[i][h] ----
    int rt = tid >> 4, ct = tid & 15;
    float acc[4][4] = {};
    #pragma unroll 16
    for (int k = 0; k < LNO; k++) {
        float mv[4];
        #pragma unroll
        for (int r = 0; r < 4; r++) mv[r] = Ls[(rt * 4 + r) * 65 + k];
        float4 xv = *reinterpret_cast<const float4*>(&As[k * LNO + ct * 4]);
        #pragma unroll
        for (int r = 0; r < 4; r++) {
            acc[r][0] += mv[r] * xv.x;
            acc[r][1] += mv[r] * xv.y;
            acc[r][2] += mv[r] * xv.z;
            acc[r][3] += mv[r] * xv.w;
        }
    }
    float dv = __ldg(&Dv[head]);
    float* ob = outp + (size_t)batch * LNO * DIN + head * HDIM;
    #pragma unroll
    for (int r = 0; r < 4; r++) {
        int i = rt * 4 + r;
        float dni = sdn[i];
        float4 xi = *reinterpret_cast<const float4*>(&As[i * LNO + ct * 4]);
        float4 v;
        v.x = acc[r][0] * dni + xi.x * dv;
        v.y = acc[r][1] * dni + xi.y * dv;
        v.z = acc[r][2] * dni + xi.z * dv;
        v.w = acc[r][3] * dni + xi.w * dv;
        *reinterpret_cast<float4*>(&ob[i * DIN + ct * 4]) = v;
    }
}

extern "C" void kernel_launch(void* const* d_in, const int* in_sizes, int n_in,
                              void* d_out, int out_size) {
    const float* x       = (const float*)d_in[0];
    const float* Bm      = (const float*)d_in[1];
    const float* Cm      = (const float*)d_in[2];
    const float* dt      = (const float*)d_in[3];
    const float* dt_edge = (const float*)d_in[4];
    const float* dt_bias = (const float*)d_in[5];
    const float* Dv      = (const float*)d_in[6];
    const float* masks   = (const float*)d_in[7];
    const int*   eidx    = (const int*)d_in[8];
    float* outp = (float*)d_out;

    k_zero_cb<<<1024, 256>>>();
    k_cb<<<BGR * 4, 256>>>(Cm, Bm);
    k_fused<<<BGR * NH, 256>>>(x, dt, dt_edge, dt_bias, Dv, masks, eidx, outp);
}

// round 6
// speedup vs baseline: 1.7273x; 1.3199x over previous
#include <cuda_runtime.h>
#include <math.h>

#define BGR 256      // batch graphs
#define LNO 64       // nodes per graph
#define NND 16384    // total nodes
#define NED 65536    // total edges
#define EPG 256      // edges per graph
#define NH  8        // heads
#define DIN 512      // d_inner
#define ST  65       // padded row stride for A/W tiles

// split-K partial CB buffers: [slice][batch][64*64]  (16 MB, static scratch)
__device__ float g_CBp[4 * (size_t)BGR * LNO * LNO];

__device__ __forceinline__ float softplusf(float x) {
    return fmaxf(x, 0.f) + log1pf(expf(-fabsf(x)));
}

// ============================================================================
// k_cb: CB[b,i,t] = dot(C[b,i,:], B[b,t,:]).  grid = batch*4 (splitK slices of
// 128), 128 threads, 8x4 thread tiles (12 LDS per 32 FFMA -> FFMA-bound),
// K-chunks of 32 (16.9 KB smem -> high occupancy). Plain stores, no atomics.
// ============================================================================
__global__ void __launch_bounds__(128) k_cb(const float* __restrict__ Cin,
                                            const float* __restrict__ Bin) {
    __shared__ float Cs[LNO * 33];
    __shared__ float Bs[LNO * 33];
    int batch = blockIdx.x >> 2, sl = blockIdx.x & 3;
    int tid = threadIdx.x;
    int cr = tid >> 4, cc = tid & 15;   // 8 row-threads x 16 col-threads
    const float* Cb = Cin + (size_t)batch * LNO * DIN;
    const float* Bb = Bin + (size_t)batch * LNO * DIN;
    float acc[8][4] = {};
    int dbeg = sl * 128;
    for (int d0 = dbeg; d0 < dbeg + 128; d0 += 32) {
        for (int i = tid; i < 512; i += 128) {
            int row = i >> 3, seg = i & 7;
            float4 cv = *reinterpret_cast<const float4*>(Cb + row * DIN + d0 + seg * 4);
            float4 bv = *reinterpret_cast<const float4*>(Bb + row * DIN + d0 + seg * 4);
            int base = row * 33 + seg * 4;
            Cs[base] = cv.x; Cs[base + 1] = cv.y; Cs[base + 2] = cv.z; Cs[base + 3] = cv.w;
            Bs[base] = bv.x; Bs[base + 1] = bv.y; Bs[base + 2] = bv.z; Bs[base + 3] = bv.w;
        }
        __syncthreads();
        #pragma unroll 8
        for (int k = 0; k < 32; k++) {
            float cv[8], bv[4];
            #pragma unroll
            for (int r = 0; r < 8; r++) cv[r] = Cs[(cr * 8 + r) * 33 + k];
            #pragma unroll
            for (int c = 0; c < 4; c++) bv[c] = Bs[(cc * 4 + c) * 33 + k];
            #pragma unroll
            for (int r = 0; r < 8; r++)
                #pragma unroll
                for (int c = 0; c < 4; c++) acc[r][c] += cv[r] * bv[c];
        }
        __syncthreads();
    }
    float* o = g_CBp + ((size_t)sl * BGR + batch) * (LNO * LNO);
    #pragma unroll
    for (int r = 0; r < 8; r++) {
        float4 v = make_float4(acc[r][0], acc[r][1], acc[r][2], acc[r][3]);
        *reinterpret_cast<float4*>(&o[(cr * 8 + r) * LNO + cc * 4]) = v;
    }
}

// ============================================================================
// k_fused: one block = (batch, head-quad).  256 threads = 4 heads x 64 cols.
// Phases: zero+CB-sum+node-softplus | edge scatter | degree-normalize |
// forward substitution (all 8 warps, L column in registers) | W=(dn*L).*CB
// (transposed, aliased over A) | per-head 64x64x64 y-GEMM + D residual.
// ============================================================================
__global__ void __launch_bounds__(256, 2) k_fused(
    const float* __restrict__ x, const float* __restrict__ dt,
    const float* __restrict__ dt_edge, const float* __restrict__ bias,
    const float* __restrict__ Dv, const float* __restrict__ mask,
    const int* __restrict__ eidx, float* __restrict__ outp)
{
    extern __shared__ float smem[];
    float* Ab   = smem;               // 4 * 64 * 65 = 16640 floats (A, then W^T)
    float* CBs  = Ab + 4 * LNO * ST;  // 4096
    float* Xs   = CBs + LNO * LNO;    // 4096
    float* sec  = Xs + LNO * LNO;     // 64
    float* sdn  = sec + LNO;          // 256  [head][i]
    float* sdts = sdn + 256;          // 256
    float* sdtt = sdts + 256;         // 256

    int batch = blockIdx.x >> 1;
    int hbase = (blockIdx.x & 1) * 4;
    int tid = threadIdx.x;

    // ---- phase 1: zero A, sum CB partials, node softplus ----
    {
        float4 z = make_float4(0.f, 0.f, 0.f, 0.f);
        for (int i = tid; i < (4 * LNO * ST) / 4; i += 256)
            reinterpret_cast<float4*>(Ab)[i] = z;
        const float4* p0 = reinterpret_cast<const float4*>(g_CBp + (size_t)batch * (LNO * LNO));
        const float4* p1 = reinterpret_cast<const float4*>(g_CBp + ((size_t)BGR + batch) * (LNO * LNO));
        const float4* p2 = reinterpret_cast<const float4*>(g_CBp + ((size_t)2 * BGR + batch) * (LNO * LNO));
        const float4* p3 = reinterpret_cast<const float4*>(g_CBp + ((size_t)3 * BGR + batch) * (LNO * LNO));
        for (int i = tid; i < (LNO * LNO) / 4; i += 256) {
            float4 a = p0[i], b = p1[i], c = p2[i], d = p3[i];
            reinterpret_cast<float4*>(CBs)[i] =
                make_float4(a.x + b.x + c.x + d.x, a.y + b.y + c.y + d.y,
                            a.z + b.z + c.z + d.z, a.w + b.w + c.w + d.w);
        }
        if (tid < LNO) sec[tid] = 0.f;
        int h = tid >> 6, t = tid & 63;
        float b = __ldg(&bias[hbase + h]);
        int node = batch * LNO + t;
        sdts[tid] = softplusf(dt[node * 16 + 2 * (hbase + h)] + b);
        sdtt[tid] = softplusf(dt[node * 16 + 2 * (hbase + h) + 1] + b);
        sdn[tid] = 0.f;
    }
    __syncthreads();

    // ---- phase 2: edge scatter (one edge per thread, 4 heads) ----
    {
        int e = batch * EPG + tid;
        int s = eidx[e] & 63;
        int d = eidx[NED + e] & 63;
        float m = mask[e];
        atomicAdd(&sec[d], m);
        #pragma unroll
        for (int h = 0; h < 4; h++) {
            float te = softplusf(dt_edge[e * NH + hbase + h] + __ldg(&bias[hbase + h]));
            float sum = (sdts[h * 64 + s] + sdtt[h * 64 + d] + te) * 0.57735026918962576f;
            atomicAdd(&Ab[h * LNO * ST + d * ST + s], expf(-sum) * m);
            atomicAdd(&sdn[h * 64 + d], sum * m);
        }
    }
    __syncthreads();

    // ---- phase 3: normalize A by sqrt(max(1, ec_i*ec_t)) ----
    for (int idx = tid; idx < LNO * LNO; idx += 256) {
        int i = idx >> 6, t = idx & 63;
        float p = sec[i] * sec[t];
        float sc = (p >= 1.f) ? rsqrtf(p) : 1.f;
        #pragma unroll
        for (int h = 0; h < 4; h++) Ab[h * LNO * ST + i * ST + t] *= sc;
    }
    __syncthreads();

    // ---- phase 4: forward substitution, L column t (head h) in registers ----
    {
        int t = tid & 63;
        int h = tid >> 6;
        const float* A = Ab + h * LNO * ST;
        float l[64];
        if ((t & 32) == 0) {
            #pragma unroll
            for (int i = 0; i < 64; i++) {
                float a0 = (i == t) ? 1.f : 0.f, a1 = 0.f, a2 = 0.f, a3 = 0.f;
                #pragma unroll
                for (int k = 0; k < i; k += 4) {
                    a0 += A[i * ST + k] * l[k];
                    if (k + 1 < i) a1 += A[i * ST + k + 1] * l[k + 1];
                    if (k + 2 < i) a2 += A[i * ST + k + 2] * l[k + 2];
                    if (k + 3 < i) a3 += A[i * ST + k + 3] * l[k + 3];
                }
                l[i] = (a0 + a1) + (a2 + a3);
            }
        } else {
            // column t>=32: L[i][t]=0 for i<32; recurrence only touches k>=32
            #pragma unroll
            for (int i = 0; i < 32; i++) l[i] = 0.f;
            #pragma unroll
            for (int i = 32; i < 64; i++) {
                float a0 = (i == t) ? 1.f : 0.f, a1 = 0.f, a2 = 0.f, a3 = 0.f;
                #pragma unroll
                for (int k = 32; k < i; k += 4) {
                    a0 += A[i * ST + k] * l[k];
                    if (k + 1 < i) a1 += A[i * ST + k + 1] * l[k + 1];
                    if (k + 2 < i) a2 += A[i * ST + k + 2] * l[k + 2];
                    if (k + 3 < i) a3 += A[i * ST + k + 3] * l[k + 3];
                }
                l[i] = (a0 + a1) + (a2 + a3);
            }
        }
        __syncthreads();   // A reads done everywhere before W overwrites it

        // ---- phase 5: W^T[t][i] = l[i] * dn[i] * CB[i][t]  (aliased over A) ----
        float* W = Ab + h * LNO * ST;
        #pragma unroll 8
        for (int i = 0; i < 64; i++)
            W[t * ST + i] = l[i] * sdn[h * 64 + i] * CBs[i * 64 + t];
    }
    __syncthreads();

    // ---- phase 6: per-head y = W @ x4 + D * x4 ----
    for (int h = 0; h < 4; h++) {
        const float* xb = x + (size_t)batch * LNO * DIN + (hbase + h) * 64;
        for (int idx = tid; idx < 1024; idx += 256) {
            int tr = idx >> 4, c4 = idx & 15;
            *reinterpret_cast<float4*>(&Xs[tr * 64 + c4 * 4]) =
                *reinterpret_cast<const float4*>(xb + tr * DIN + c4 * 4);
        }
        __syncthreads();
        int rt = tid >> 4, ct = tid & 15;
        const float* W = Ab + h * LNO * ST;   // W^T layout: [k][i]
        float acc[4][4] = {};
        #pragma unroll 8
        for (int k = 0; k < 64; k++) {
            float mv[4];
            #pragma unroll
            for (int r = 0; r < 4; r++) mv[r] = W[k * ST + rt * 4 + r];
            float4 xv = *reinterpret_cast<const float4*>(&Xs[k * 64 + ct * 4]);
            #pragma unroll
            for (int r = 0; r < 4; r++) {
                acc[r][0] += mv[r] * xv.x;
                acc[r][1] += mv[r] * xv.y;
                acc[r][2] += mv[r] * xv.z;
                acc[r][3] += mv[r] * xv.w;
            }
        }
        float dv = __ldg(&Dv[hbase + h]);
        float* ob = outp + (size_t)batch * LNO * DIN + (hbase + h) * 64;
        #pragma unroll
        for (int r = 0; r < 4; r++) {
            int i = rt * 4 + r;
            float4 xi = *reinterpret_cast<const float4*>(&Xs[i * 64 + ct * 4]);
            float4 v;
            v.x = acc[r][0] + xi.x * dv;
            v.y = acc[r][1] + xi.y * dv;
            v.z = acc[r][2] + xi.z * dv;
            v.w = acc[r][3] + xi.w * dv;
            *reinterpret_cast<float4*>(&ob[i * DIN + ct * 4]) = v;
        }
        __syncthreads();
    }
}

static const int FUSED_SMEM = (4 * LNO * ST + 2 * LNO * LNO + LNO + 3 * 256) * 4;

extern "C" void kernel_launch(void* const* d_in, const int* in_sizes, int n_in,
                              void* d_out, int out_size) {
    const float* x       = (const float*)d_in[0];
    const float* Bm      = (const float*)d_in[1];
    const float* Cm      = (const float*)d_in[2];
    const float* dt      = (const float*)d_in[3];
    const float* dt_edge = (const float*)d_in[4];
    const float* dt_bias = (const float*)d_in[5];
    const float* Dv      = (const float*)d_in[6];
    const float* masks   = (const float*)d_in[7];
    const int*   eidx    = (const int*)d_in[8];
    float* outp = (float*)d_out;

    cudaFuncSetAttribute(k_fused, cudaFuncAttributeMaxDynamicSharedMemorySize, FUSED_SMEM);
    k_cb<<<BGR * 4, 128>>>(Cm, Bm);
    k_fused<<<BGR * 2, 256, FUSED_SMEM>>>(x, dt, dt_edge, dt_bias, Dv, masks, eidx, outp);
}

// round 8
// speedup vs baseline: 2.3061x; 1.3351x over previous
#include <cuda_runtime.h>
#include <math.h>

#define BGR 256      // batch graphs
#define LNO 64       // nodes per graph
#define NND 16384    // total nodes
#define NED 65536    // total edges
#define EPG 256      // edges per graph
#define NH  8        // heads
#define DIN 512      // d_inner
#define ST  68       // padded row stride (mult of 4: float4-aligned, 4-way banks)

typedef unsigned long long u64;

// split-K partial CB buffers (transposed [t][i] layout): 16 MB static scratch
__device__ float g_CBp[4 * (size_t)BGR * LNO * LNO];

__device__ __forceinline__ float softplusf(float x) {
    return fmaxf(x, 0.f) + log1pf(expf(-fabsf(x)));
}
__device__ __forceinline__ u64 pack2(float v) {
    unsigned r = __float_as_uint(v);
    u64 o;
    asm("mov.b64 %0, {%1, %1};" : "=l"(o) : "r"(r));
    return o;
}
__device__ __forceinline__ void fma2(u64& d, u64 a, u64 b) {
    asm("fma.rn.f32x2 %0, %1, %2, %3;" : "=l"(d) : "l"(a), "l"(b), "l"(d));
}
__device__ __forceinline__ float2 unpack2(u64 v) {
    float2 f;
    asm("mov.b64 {%0, %1}, %2;" : "=f"(f.x), "=f"(f.y) : "l"(v));
    return f;
}

// ============================================================================
// k_cb: CBt[b][t][i] = dot(C[b,i,:], B[b,t,:]), splitK=4 slices of 128.
// Smem tiles transposed to [k][row] (stride 68) so the C operand loads as
// LDS.128 pairs; inner loop = 3 LDS.128 + 4 packs + 16 FMA2 per 32 MACs.
// ============================================================================
__global__ void __launch_bounds__(128) k_cb(const float* __restrict__ Cin,
                                            const float* __restrict__ Bin) {
    __shared__ __align__(16) float Cs[32 * ST];
    __shared__ __align__(16) float Bs[32 * ST];
    int batch = blockIdx.x >> 2, sl = blockIdx.x & 3;
    int tid = threadIdx.x;
    int cr = tid >> 4, cc = tid & 15;         // 8 i-groups x 16 t-groups
    const float* Cb = Cin + (size_t)batch * LNO * DIN;
    const float* Bb = Bin + (size_t)batch * LNO * DIN;
    u64 acc[4][4] = {};                        // [i-pair][t], f32x2 over i
    int dbeg = sl * 128;
    for (int d0 = dbeg; d0 < dbeg + 128; d0 += 32) {
        for (int i = tid; i < 512; i += 128) {
            int row = i >> 3, seg = i & 7;
            float4 cv = *reinterpret_cast<const float4*>(Cb + row * DIN + d0 + seg * 4);
            float4 bv = *reinterpret_cast<const float4*>(Bb + row * DIN + d0 + seg * 4);
            Cs[(seg * 4 + 0) * ST + row] = cv.x; Cs[(seg * 4 + 1) * ST + row] = cv.y;
            Cs[(seg * 4 + 2) * ST + row] = cv.z; Cs[(seg * 4 + 3) * ST + row] = cv.w;
            Bs[(seg * 4 + 0) * ST + row] = bv.x; Bs[(seg * 4 + 1) * ST + row] = bv.y;
            Bs[(seg * 4 + 2) * ST + row] = bv.z; Bs[(seg * 4 + 3) * ST + row] = bv.w;
        }
        __syncthreads();
        #pragma unroll 8
        for (int kk = 0; kk < 32; kk++) {
            const float* cp = &Cs[kk * ST + cr * 8];
            ulonglong2 q0 = *reinterpret_cast<const ulonglong2*>(cp);
            ulonglong2 q1 = *reinterpret_cast<const ulonglong2*>(cp + 4);
            float4 bv = *reinterpret_cast<const float4*>(&Bs[kk * ST + cc * 4]);
            u64 b0 = pack2(bv.x), b1 = pack2(bv.y), b2 = pack2(bv.z), b3 = pack2(bv.w);
            fma2(acc[0][0], q0.x, b0); fma2(acc[0][1], q0.x, b1);
            fma2(acc[0][2], q0.x, b2); fma2(acc[0][3], q0.x, b3);
            fma2(acc[1][0], q0.y, b0); fma2(acc[1][1], q0.y, b1);
            fma2(acc[1][2], q0.y, b2); fma2(acc[1][3], q0.y, b3);
            fma2(acc[2][0], q1.x, b0); fma2(acc[2][1], q1.x, b1);
            fma2(acc[2][2], q1.x, b2); fma2(acc[2][3], q1.x, b3);
            fma2(acc[3][0], q1.y, b0); fma2(acc[3][1], q1.y, b1);
            fma2(acc[3][2], q1.y, b2); fma2(acc[3][3], q1.y, b3);
        }
        __syncthreads();
    }
    // store transposed partial: row t = cc*4+c, cols i = cr*8..cr*8+7
    float* o = g_CBp + ((size_t)sl * BGR + batch) * (LNO * LNO);
    #pragma unroll
    for (int c = 0; c < 4; c++) {
        float2 f0 = unpack2(acc[0][c]), f1 = unpack2(acc[1][c]);
        float2 f2 = unpack2(acc[2][c]), f3 = unpack2(acc[3][c]);
        float* row = o + (cc * 4 + c) * LNO + cr * 8;
        *reinterpret_cast<float4*>(row)     = make_float4(f0.x, f0.y, f1.x, f1.y);
        *reinterpret_cast<float4*>(row + 4) = make_float4(f2.x, f2.y, f3.x, f3.y);
    }
}

// ============================================================================
// k_fused: block = (batch, head-quad), 256 threads.
// ============================================================================
__global__ void __launch_bounds__(256, 2) k_fused(
    const float* __restrict__ x, const float* __restrict__ dt,
    const float* __restrict__ dt_edge, const float* __restrict__ bias,
    const float* __restrict__ Dv, const float* __restrict__ mask,
    const int* __restrict__ eidx, float* __restrict__ outp)
{
    extern __shared__ __align__(16) float smem[];
    float* Ab  = smem;                         // 4*64*68 = 17408 (A, then W^T)
    float* rg2 = Ab + 4 * LNO * ST;            // union region, 8192 floats
    float* CBt = rg2;                          // 64*68 = 4352 (phases 1-5)
    float* sec  = CBt + LNO * ST;              // 64
    float* sdn  = sec + LNO;                   // 256 [head][i]
    float* sdts = sdn + 256;                   // 256
    float* sdtt = sdts + 256;                  // 256
    float* Xs  = rg2;                          // phase 6: 2 heads x 4096

    int batch = blockIdx.x >> 1;
    int hbase = (blockIdx.x & 1) * 4;
    int tid = threadIdx.x;

    // ---- phase 1: zero A, sum CB partials (transposed, stride-68), softplus ----
    {
        float4 z = make_float4(0.f, 0.f, 0.f, 0.f);
        for (int i = tid; i < (4 * LNO * ST) / 4; i += 256)
            reinterpret_cast<float4*>(Ab)[i] = z;
        const float4* p0 = reinterpret_cast<const float4*>(g_CBp + (size_t)batch * (LNO * LNO));
        const float4* p1 = reinterpret_cast<const float4*>(g_CBp + ((size_t)BGR + batch) * (LNO * LNO));
        const float4* p2 = reinterpret_cast<const float4*>(g_CBp + ((size_t)2 * BGR + batch) * (LNO * LNO));
        const float4* p3 = reinterpret_cast<const float4*>(g_CBp + ((size_t)3 * BGR + batch) * (LNO * LNO));
        for (int i = tid; i < 1024; i += 256) {
            int t = i >> 4, c4 = i & 15;
            float4 a = p0[i], b = p1[i], c = p2[i], d = p3[i];
            *reinterpret_cast<float4*>(&CBt[t * ST + c4 * 4]) =
                make_float4(a.x + b.x + c.x + d.x, a.y + b.y + c.y + d.y,
                            a.z + b.z + c.z + d.z, a.w + b.w + c.w + d.w);
        }
        if (tid < LNO) sec[tid] = 0.f;
        int h = tid >> 6, t = tid & 63;
        float b = __ldg(&bias[hbase + h]);
        int node = batch * LNO + t;
        sdts[tid] = softplusf(dt[node * 16 + 2 * (hbase + h)] + b);
        sdtt[tid] = softplusf(dt[node * 16 + 2 * (hbase + h) + 1] + b);
        sdn[tid] = 0.f;
    }
    __syncthreads();

    // ---- phase 2: edge scatter ----
    {
        int e = batch * EPG + tid;
        int s = eidx[e] & 63;
        int d = eidx[NED + e] & 63;
        float m = mask[e];
        atomicAdd(&sec[d], m);
        #pragma unroll
        for (int h = 0; h < 4; h++) {
            float te = softplusf(dt_edge[e * NH + hbase + h] + __ldg(&bias[hbase + h]));
            float sum = (sdts[h * 64 + s] + sdtt[h * 64 + d] + te) * 0.57735026918962576f;
            atomicAdd(&Ab[h * LNO * ST + d * ST + s], expf(-sum) * m);
            atomicAdd(&sdn[h * 64 + d], sum * m);
        }
    }
    __syncthreads();

    // ---- phase 3: normalize ----
    for (int idx = tid; idx < LNO * LNO; idx += 256) {
        int i = idx >> 6, t = idx & 63;
        float p = sec[i] * sec[t];
        float sc = (p >= 1.f) ? rsqrtf(p) : 1.f;
        #pragma unroll
        for (int h = 0; h < 4; h++) Ab[h * LNO * ST + i * ST + t] *= sc;
    }
    __syncthreads();

    // ---- phase 4: forward substitution (L column in registers) ----
    {
        int t = tid & 63;
        int h = tid >> 6;
        const float* A = Ab + h * LNO * ST;
        float l[64];
        if ((t & 32) == 0) {
            #pragma unroll
            for (int i = 0; i < 64; i++) {
                float a0 = (i == t) ? 1.f : 0.f, a1 = 0.f, a2 = 0.f, a3 = 0.f;
                #pragma unroll
                for (int k = 0; k < i; k += 4) {
                    a0 += A[i * ST + k] * l[k];
                    if (k + 1 < i) a1 += A[i * ST + k + 1] * l[k + 1];
                    if (k + 2 < i) a2 += A[i * ST + k + 2] * l[k + 2];
                    if (k + 3 < i) a3 += A[i * ST + k + 3] * l[k + 3];
                }
                l[i] = (a0 + a1) + (a2 + a3);
            }
        } else {
            #pragma unroll
            for (int i = 0; i < 32; i++) l[i] = 0.f;
            #pragma unroll
            for (int i = 32; i < 64; i++) {
                float a0 = (i == t) ? 1.f : 0.f, a1 = 0.f, a2 = 0.f, a3 = 0.f;
                #pragma unroll
                for (int k = 32; k < i; k += 4) {
                    a0 += A[i * ST + k] * l[k];
                    if (k + 1 < i) a1 += A[i * ST + k + 1] * l[k + 1];
                    if (k + 2 < i) a2 += A[i * ST + k + 2] * l[k + 2];
                    if (k + 3 < i) a3 += A[i * ST + k + 3] * l[k + 3];
                }
                l[i] = (a0 + a1) + (a2 + a3);
            }
        }
        __syncthreads();   // A reads done before W overwrites

        // ---- phase 5: W^T[t][i] = l[i]*dn[i]*CBt[t][i] (all float4) ----
        float* W = Ab + h * LNO * ST + t * ST;
        const float* cbp = CBt + t * ST;
        const float* dnp = sdn + h * 64;
        #pragma unroll
        for (int ib = 0; ib < 16; ib++) {
            float4 cb4 = *reinterpret_cast<const float4*>(cbp + ib * 4);
            float4 dn4 = *reinterpret_cast<const float4*>(dnp + ib * 4);
            float4 w4;
            w4.x = l[ib * 4 + 0] * dn4.x * cb4.x;
            w4.y = l[ib * 4 + 1] * dn4.y * cb4.y;
            w4.z = l[ib * 4 + 2] * dn4.z * cb4.z;
            w4.w = l[ib * 4 + 3] * dn4.w * cb4.w;
            *reinterpret_cast<float4*>(W + ib * 4) = w4;
        }
    }
    __syncthreads();

    // ---- phase 6: head pairs, y = W @ x4 + D*x4, FMA2 inner loop ----
    for (int pair = 0; pair < 2; pair++) {
        const float* xb = x + (size_t)batch * LNO * DIN + (hbase + pair * 2) * 64;
        for (int idx = tid; idx < 2048; idx += 256) {
            int hh = idx >> 10;
            int rem = idx & 1023;
            int tr = rem >> 4, c4 = rem & 15;
            *reinterpret_cast<float4*>(&Xs[hh * 4096 + tr * 64 + c4 * 4]) =
                *reinterpret_cast<const float4*>(xb + hh * 64 + tr * DIN + c4 * 4);
        }
        __syncthreads();
        int hloc = tid >> 7;
        int t128 = tid & 127;
        int rt = t128 >> 4, ct = t128 & 15;     // 8 i-groups x 16 c-groups
        const float* W = Ab + (pair * 2 + hloc) * LNO * ST;
        const float* Xh = Xs + hloc * 4096;
        u64 acc[4][4] = {};                      // [i-pair][c]
        #pragma unroll 8
        for (int k = 0; k < 64; k++) {
            const float* wp = &W[k * ST + rt * 8];
            ulonglong2 q0 = *reinterpret_cast<const ulonglong2*>(wp);
            ulonglong2 q1 = *reinterpret_cast<const ulonglong2*>(wp + 4);
            float4 xv = *reinterpret_cast<const float4*>(&Xh[k * 64 + ct * 4]);
            u64 x0 = pack2(xv.x), x1 = pack2(xv.y), x2 = pack2(xv.z), x3 = pack2(xv.w);
            fma2(acc[0][0], q0.x, x0); fma2(acc[0][1], q0.x, x1);
            fma2(acc[0][2], q0.x, x2); fma2(acc[0][3], q0.x, x3);
            fma2(acc[1][0], q0.y, x0); fma2(acc[1][1], q0.y, x1);
            fma2(acc[1][2], q0.y, x2); fma2(acc[1][3], q0.y, x3);
            fma2(acc[2][0], q1.x, x0); fma2(acc[2][1], q1.x, x1);
            fma2(acc[2][2], q1.x, x2); fma2(acc[2][3], q1.x, x3);
            fma2(acc[3][0], q1.y, x0); fma2(acc[3][1], q1.y, x1);
            fma2(acc[3][2], q1.y, x2); fma2(acc[3][3], q1.y, x3);
        }
        float dv = __ldg(&Dv[hbase + pair * 2 + hloc]);
        float* ob = outp + (size_t)batch * LNO * DIN + (hbase + pair * 2 + hloc) * 64;
        #pragma unroll
        for (int ip = 0; ip < 4; ip++) {
            int i0 = rt * 8 + ip * 2;
            float2 a0 = unpack2(acc[ip][0]), a1 = unpack2(acc[ip][1]);
            float2 a2 = unpack2(acc[ip][2]), a3 = unpack2(acc[ip][3]);
            float4 xi0 = *reinterpret_cast<const float4*>(&Xh[i0 * 64 + ct * 4]);
            float4 xi1 = *reinterpret_cast<const float4*>(&Xh[(i0 + 1) * 64 + ct * 4]);
            float4 v0, v1;
            v0.x = a0.x + xi0.x * dv; v0.y = a1.x + xi0.y * dv;
            v0.z = a2.x + xi0.z * dv; v0.w = a3.x + xi0.w * dv;
            v1.x = a0.y + xi1.x * dv; v1.y = a1.y + xi1.y * dv;
            v1.z = a2.y + xi1.z * dv; v1.w = a3.y + xi1.w * dv;
            *reinterpret_cast<float4*>(&ob[i0 * DIN + ct * 4]) = v0;
            *reinterpret_cast<float4*>(&ob[(i0 + 1) * DIN + ct * 4]) = v1;
        }
        __syncthreads();
    }
}

static const int FUSED_SMEM = (4 * LNO * ST + 8192) * 4;   // 102400 bytes

extern "C" void kernel_launch(void* const* d_in, const int* in_sizes, int n_in,
                              void* d_out, int out_size) {
    const float* x       = (const float*)d_in[0];
    const float* Bm      = (const float*)d_in[1];
    const float* Cm      = (const float*)d_in[2];
    const float* dt      = (const float*)d_in[3];
    const float* dt_edge = (const float*)d_in[4];
    const float* dt_bias = (const float*)d_in[5];
    const float* Dv      = (const float*)d_in[6];
    const float* masks   = (const float*)d_in[7];
    const int*   eidx    = (const int*)d_in[8];
    float* outp = (float*)d_out;

    cudaFuncSetAttribute(k_fused, cudaFuncAttributeMaxDynamicSharedMemorySize, FUSED_SMEM);
    k_cb<<<BGR * 4, 128>>>(Cm, Bm);
    k_fused<<<BGR * 2, 256, FUSED_SMEM>>>(x, dt, dt_edge, dt_bias, Dv, masks, eidx, outp);
}

// round 15
// speedup vs baseline: 2.5416x; 1.1021x over previous
#include <cuda_runtime.h>
#include <cuda_bf16.h>
#include <math.h>
#include <cstdint>

#define BGR 256      // batch graphs
#define LNO 64       // nodes per graph
#define NND 16384
#define NED 65536
#define EPG 256
#define NH  8
#define DIN 512
#define ST  68       // padded stride for fp32 smem tiles
#define SK  72       // bf16 smem K-stride (bank-conflict-free fragment loads)

typedef unsigned long long u64;

// CB scratch: [batch][t][i] (transposed), 4 MB
__device__ float g_CB[(size_t)BGR * LNO * LNO];

__device__ __forceinline__ float softplusf(float x) {
    return fmaxf(x, 0.f) + log1pf(expf(-fabsf(x)));
}
__device__ __forceinline__ u64 pack2(float v) {
    unsigned r = __float_as_uint(v);
    u64 o;
    asm("mov.b64 %0, {%1, %1};" : "=l"(o) : "r"(r));
    return o;
}
__device__ __forceinline__ void fma2(u64& d, u64 a, u64 b) {
    asm("fma.rn.f32x2 %0, %1, %2, %3;" : "=l"(d) : "l"(a), "l"(b), "l"(d));
}
__device__ __forceinline__ float2 unpack2(u64 v) {
    float2 f;
    asm("mov.b64 {%0, %1}, %2;" : "=f"(f.x), "=f"(f.y) : "l"(v));
    return f;
}

// warp-level bf16 MMA (baseline PTX, works on plain sm_103 target)
__device__ __forceinline__ void mma16816(float* d, const uint32_t* a,
                                         uint32_t b0, uint32_t b1) {
    asm volatile(
        "mma.sync.aligned.m16n8k16.row.col.f32.bf16.bf16.f32 "
        "{%0,%1,%2,%3}, {%4,%5,%6,%7}, {%8,%9}, {%0,%1,%2,%3};"
        : "+f"(d[0]), "+f"(d[1]), "+f"(d[2]), "+f"(d[3])
        : "r"(a[0]), "r"(a[1]), "r"(a[2]), "r"(a[3]), "r"(b0), "r"(b1));
}

__device__ __forceinline__ void store_hilo(__nv_bfloat16* hi, __nv_bfloat16* lo,
                                           int row, int kq, float4 v) {
    __nv_bfloat162 h0 = __float22bfloat162_rn(make_float2(v.x, v.y));
    __nv_bfloat162 h1 = __float22bfloat162_rn(make_float2(v.z, v.w));
    float2 f0 = __bfloat1622float2(h0);
    float2 f1 = __bfloat1622float2(h1);
    __nv_bfloat162 l0 = __float22bfloat162_rn(make_float2(v.x - f0.x, v.y - f0.y));
    __nv_bfloat162 l1 = __float22bfloat162_rn(make_float2(v.z - f1.x, v.w - f1.y));
    int e = row * SK + kq * 4;
    *reinterpret_cast<uint32_t*>(hi + e)     = *reinterpret_cast<uint32_t*>(&h0);
    *reinterpret_cast<uint32_t*>(hi + e + 2) = *reinterpret_cast<uint32_t*>(&h1);
    *reinterpret_cast<uint32_t*>(lo + e)     = *reinterpret_cast<uint32_t*>(&l0);
    *reinterpret_cast<uint32_t*>(lo + e + 2) = *reinterpret_cast<uint32_t*>(&l1);
}
__device__ __forceinline__ uint32_t ld32(const __nv_bfloat16* p, int row, int col) {
    return *reinterpret_cast<const uint32_t*>(p + row * SK + col);
}

// ============================================================================
// k_cb_mma: CBt[b][t][i] = dot(C[b,i,:], B[b,t,:]) via bf16 split mma.sync.
// Block = 1 batch, 8 warps; warp owns 16x32 of the 64x64 output.
// 3 split terms (hh, hl, lh); dropped lo*lo term ~2^-16 relative.
// ============================================================================
__global__ void __launch_bounds__(256) k_cb_mma(const float* __restrict__ Cin,
                                                const float* __restrict__ Bin) {
    extern __shared__ __align__(16) unsigned char sm[];
    __nv_bfloat16* Chi = reinterpret_cast<__nv_bfloat16*>(sm);   // 64*72
    __nv_bfloat16* Clo = Chi + LNO * SK;
    __nv_bfloat16* Bhi = Clo + LNO * SK;
    __nv_bfloat16* Blo = Bhi + LNO * SK;
    float* Dt = reinterpret_cast<float*>(sm);                    // reused after

    int batch = blockIdx.x;
    int tid = threadIdx.x, w = tid >> 5, l = tid & 31;
    const float* Cb = Cin + (size_t)batch * LNO * DIN;
    const float* Bb = Bin + (size_t)batch * LNO * DIN;

    int gr = (w & 3) * 16;     // output row (i) base
    int gc = (w >> 2) * 32;    // output col (t) base
    float acc[4][4] = {};      // [ntile][frag]

    for (int ch = 0; ch < 8; ch++) {
        int k0 = ch * 64;
        #pragma unroll
        for (int j = 0; j < 4; j++) {
            int idx = tid + j * 256;
            int row = idx >> 4, kq = idx & 15;
            float4 cv = *reinterpret_cast<const float4*>(Cb + row * DIN + k0 + kq * 4);
            float4 bv = *reinterpret_cast<const float4*>(Bb + row * DIN + k0 + kq * 4);
            store_hilo(Chi, Clo, row, kq, cv);
            store_hilo(Bhi, Blo, row, kq, bv);
        }
        __syncthreads();
        #pragma unroll
        for (int ks = 0; ks < 4; ks++) {
            int ar = gr + (l >> 2);
            int ac = ks * 16 + (l & 3) * 2;
            uint32_t ah[4], al[4];
            ah[0] = ld32(Chi, ar, ac);     ah[1] = ld32(Chi, ar + 8, ac);
            ah[2] = ld32(Chi, ar, ac + 8); ah[3] = ld32(Chi, ar + 8, ac + 8);
            al[0] = ld32(Clo, ar, ac);     al[1] = ld32(Clo, ar + 8, ac);
            al[2] = ld32(Clo, ar, ac + 8); al[3] = ld32(Clo, ar + 8, ac + 8);
            #pragma unroll
            for (int nt = 0; nt < 4; nt++) {
                int tr = gc + nt * 8 + (l >> 2);
                uint32_t bh0 = ld32(Bhi, tr, ac), bh1 = ld32(Bhi, tr, ac + 8);
                uint32_t bl0 = ld32(Blo, tr, ac), bl1 = ld32(Blo, tr, ac + 8);
                mma16816(acc[nt], ah, bh0, bh1);
                mma16816(acc[nt], ah, bl0, bl1);
                mma16816(acc[nt], al, bh0, bh1);
            }
        }
        __syncthreads();
    }

    // stage D transposed into smem: Dt[t][i], stride 68
    #pragma unroll
    for (int nt = 0; nt < 4; nt++) {
        int i0 = gr + (l >> 2);
        int t0 = gc + nt * 8 + (l & 3) * 2;
        Dt[t0 * ST + i0]           = acc[nt][0];
        Dt[(t0 + 1) * ST + i0]     = acc[nt][1];
        Dt[t0 * ST + i0 + 8]       = acc[nt][2];
        Dt[(t0 + 1) * ST + i0 + 8] = acc[nt][3];
    }
    __syncthreads();
    float* o = g_CB + (size_t)batch * 4096;
    for (int i = tid; i < 1024; i += 256) {
        int t = i >> 4, c4 = i & 15;
        *reinterpret_cast<float4*>(o + t * 64 + c4 * 4) =
            *reinterpret_cast<const float4*>(Dt + t * ST + c4 * 4);
    }
}

static const int CBMMA_SMEM = 4 * LNO * SK * 2;   // 36864 bytes (>= Dt 17408)

// ============================================================================
// k_fused: block = (batch, head-quad), 256 threads.
// ============================================================================
__global__ void __launch_bounds__(256, 2) k_fused(
    const float* __restrict__ x, const float* __restrict__ dt,
    const float* __restrict__ dt_edge, const float* __restrict__ bias,
    const float* __restrict__ Dv, const float* __restrict__ mask,
    const int* __restrict__ eidx, float* __restrict__ outp)
{
    extern __shared__ __align__(16) float smem[];
    float* Ab  = smem;                         // 4*64*68 (A, then W^T)
    float* rg2 = Ab + 4 * LNO * ST;            // union region, 8192 floats
    float* CBt = rg2;                          // 64*68 (phases 1-5)
    float* sec  = CBt + LNO * ST;              // 64
    float* sdn  = sec + LNO;                   // 256 [head][i]
    float* sdts = sdn + 256;                   // 256
    float* sdtt = sdts + 256;                  // 256
    float* Xs  = rg2;                          // phase 6: 2 heads x 4096

    int batch = blockIdx.x >> 1;
    int hbase = (blockIdx.x & 1) * 4;
    int tid = threadIdx.x;

    // ---- phase 1: zero A, copy CBt, node softplus ----
    {
        float4 z = make_float4(0.f, 0.f, 0.f, 0.f);
        for (int i = tid; i < (4 * LNO * ST) / 4; i += 256)
            reinterpret_cast<float4*>(Ab)[i] = z;
        const float4* p0 = reinterpret_cast<const float4*>(g_CB + (size_t)batch * 4096);
        for (int i = tid; i < 1024; i += 256) {
            int t = i >> 4, c4 = i & 15;
            *reinterpret_cast<float4*>(&CBt[t * ST + c4 * 4]) = p0[i];
        }
        if (tid < LNO) sec[tid] = 0.f;
        int h = tid >> 6, t = tid & 63;
        float b = __ldg(&bias[hbase + h]);
        int node = batch * LNO + t;
        sdts[tid] = softplusf(dt[node * 16 + 2 * (hbase + h)] + b);
        sdtt[tid] = softplusf(dt[node * 16 + 2 * (hbase + h) + 1] + b);
        sdn[tid] = 0.f;
    }
    __syncthreads();

    // ---- phase 2: edge scatter ----
    {
        int e = batch * EPG + tid;
        int s = eidx[e] & 63;
        int d = eidx[NED + e] & 63;
        float m = mask[e];
        atomicAdd(&sec[d], m);
        #pragma unroll
        for (int h = 0; h < 4; h++) {
            float te = softplusf(dt_edge[e * NH + hbase + h] + __ldg(&bias[hbase + h]));
            float sum = (sdts[h * 64 + s] + sdtt[h * 64 + d] + te) * 0.57735026918962576f;
            atomicAdd(&Ab[h * LNO * ST + d * ST + s], expf(-sum) * m);
            atomicAdd(&sdn[h * 64 + d], sum * m);
        }
    }
    __syncthreads();

    // ---- phase 3: normalize ----
    for (int idx = tid; idx < LNO * LNO; idx += 256) {
        int i = idx >> 6, t = idx & 63;
        float p = sec[i] * sec[t];
        float sc = (p >= 1.f) ? rsqrtf(p) : 1.f;
        #pragma unroll
        for (int h = 0; h < 4; h++) Ab[h * LNO * ST + i * ST + t] *= sc;
    }
    __syncthreads();

    // ---- phase 4: forward substitution (L column in registers) ----
    {
        int t = tid & 63;
        int h = tid >> 6;
        const float* A = Ab + h * LNO * ST;
        float l[64];
        if ((t & 32) == 0) {
            #pragma unroll
            for (int i = 0; i < 64; i++) {
                float a0 = (i == t) ? 1.f : 0.f, a1 = 0.f, a2 = 0.f, a3 = 0.f;
                #pragma unroll
                for (int k = 0; k < i; k += 4) {
                    a0 += A[i * ST + k] * l[k];
                    if (k + 1 < i) a1 += A[i * ST + k + 1] * l[k + 1];
                    if (k + 2 < i) a2 += A[i * ST + k + 2] * l[k + 2];
                    if (k + 3 < i) a3 += A[i * ST + k + 3] * l[k + 3];
                }
                l[i] = (a0 + a1) + (a2 + a3);
            }
        } else {
            #pragma unroll
            for (int i = 0; i < 32; i++) l[i] = 0.f;
            #pragma unroll
            for (int i = 32; i < 64; i++) {
                float a0 = (i == t) ? 1.f : 0.f, a1 = 0.f, a2 = 0.f, a3 = 0.f;
                #pragma unroll
                for (int k = 32; k < i; k += 4) {
                    a0 += A[i * ST + k] * l[k];
                    if (k + 1 < i) a1 += A[i * ST + k + 1] * l[k + 1];
                    if (k + 2 < i) a2 += A[i * ST + k + 2] * l[k + 2];
                    if (k + 3 < i) a3 += A[i * ST + k + 3] * l[k + 3];
                }
                l[i] = (a0 + a1) + (a2 + a3);
            }
        }
        __syncthreads();   // A reads done before W overwrites

        // ---- phase 5: W^T[t][i] = l[i]*dn[i]*CBt[t][i] ----
        float* W = Ab + h * LNO * ST + t * ST;
        const float* cbp = CBt + t * ST;
        const float* dnp = sdn + h * 64;
        #pragma unroll
        for (int ib = 0; ib < 16; ib++) {
            float4 cb4 = *reinterpret_cast<const float4*>(cbp + ib * 4);
            float4 dn4 = *reinterpret_cast<const float4*>(dnp + ib * 4);
            float4 w4;
            w4.x = l[ib * 4 + 0] * dn4.x * cb4.x;
            w4.y = l[ib * 4 + 1] * dn4.y * cb4.y;
            w4.z = l[ib * 4 + 2] * dn4.z * cb4.z;
            w4.w = l[ib * 4 + 3] * dn4.w * cb4.w;
            *reinterpret_cast<float4*>(W + ib * 4) = w4;
        }
    }
    __syncthreads();

    // ---- phase 6: head pairs, y = W @ x4 + D*x4, FMA2 inner loop ----
    for (int pair = 0; pair < 2; pair++) {
        const float* xb = x + (size_t)batch * LNO * DIN + (hbase + pair * 2) * 64;
        for (int idx = tid; idx < 2048; idx += 256) {
            int hh = idx >> 10;
            int rem = idx & 1023;
            int tr = rem >> 4, c4 = rem & 15;
            *reinterpret_cast<float4*>(&Xs[hh * 4096 + tr * 64 + c4 * 4]) =
                *reinterpret_cast<const float4*>(xb + hh * 64 + tr * DIN + c4 * 4);
        }
        __syncthreads();
        int hloc = tid >> 7;
        int t128 = tid & 127;
        int rt = t128 >> 4, ct = t128 & 15;
        const float* W = Ab + (pair * 2 + hloc) * LNO * ST;
        const float* Xh = Xs + hloc * 4096;
        u64 acc[4][4] = {};
        #pragma unroll 8
        for (int k = 0; k < 64; k++) {
            const float* wp = &W[k * ST + rt * 8];
            ulonglong2 q0 = *reinterpret_cast<const ulonglong2*>(wp);
            ulonglong2 q1 = *reinterpret_cast<const ulonglong2*>(wp + 4);
            float4 xv = *reinterpret_cast<const float4*>(&Xh[k * 64 + ct * 4]);
            u64 x0 = pack2(xv.x), x1 = pack2(xv.y), x2 = pack2(xv.z), x3 = pack2(xv.w);
            fma2(acc[0][0], q0.x, x0); fma2(acc[0][1], q0.x, x1);
            fma2(acc[0][2], q0.x, x2); fma2(acc[0][3], q0.x, x3);
            fma2(acc[1][0], q0.y, x0); fma2(acc[1][1], q0.y, x1);
            fma2(acc[1][2], q0.y, x2); fma2(acc[1][3], q0.y, x3);
            fma2(acc[2][0], q1.x, x0); fma2(acc[2][1], q1.x, x1);
            fma2(acc[2][2], q1.x, x2); fma2(acc[2][3], q1.x, x3);
            fma2(acc[3][0], q1.y, x0); fma2(acc[3][1], q1.y, x1);
            fma2(acc[3][2], q1.y, x2); fma2(acc[3][3], q1.y, x3);
        }
        float dv = __ldg(&Dv[hbase + pair * 2 + hloc]);
        float* ob = outp + (size_t)batch * LNO * DIN + (hbase + pair * 2 + hloc) * 64;
        #pragma unroll
        for (int ip = 0; ip < 4; ip++) {
            int i0 = rt * 8 + ip * 2;
            float2 a0 = unpack2(acc[ip][0]), a1 = unpack2(acc[ip][1]);
            float2 a2 = unpack2(acc[ip][2]), a3 = unpack2(acc[ip][3]);
            float4 xi0 = *reinterpret_cast<const float4*>(&Xh[i0 * 64 + ct * 4]);
            float4 xi1 = *reinterpret_cast<const float4*>(&Xh[(i0 + 1) * 64 + ct * 4]);
            float4 v0, v1;
            v0.x = a0.x + xi0.x * dv; v0.y = a1.x + xi0.y * dv;
            v0.z = a2.x + xi0.z * dv; v0.w = a3.x + xi0.w * dv;
            v1.x = a0.y + xi1.x * dv; v1.y = a1.y + xi1.y * dv;
            v1.z = a2.y + xi1.z * dv; v1.w = a3.y + xi1.w * dv;
            *reinterpret_cast<float4*>(&ob[i0 * DIN + ct * 4]) = v0;
            *reinterpret_cast<float4*>(&ob[(i0 + 1) * DIN + ct * 4]) = v1;
        }
        __syncthreads();
    }
}

static const int FUSED_SMEM = (4 * LNO * ST + 8192) * 4;   // 102400 bytes

extern "C" void kernel_launch(void* const* d_in, const int* in_sizes, int n_in,
                              void* d_out, int out_size) {
    const float* x       = (const float*)d_in[0];
    const float* Bm      = (const float*)d_in[1];
    const float* Cm      = (const float*)d_in[2];
    const float* dt      = (const float*)d_in[3];
    const float* dt_edge = (const float*)d_in[4];
    const float* dt_bias = (const float*)d_in[5];
    const float* Dv      = (const float*)d_in[6];
    const float* masks   = (const float*)d_in[7];
    const int*   eidx    = (const int*)d_in[8];
    float* outp = (float*)d_out;

    cudaFuncSetAttribute(k_cb_mma, cudaFuncAttributeMaxDynamicSharedMemorySize, CBMMA_SMEM);
    cudaFuncSetAttribute(k_fused, cudaFuncAttributeMaxDynamicSharedMemorySize, FUSED_SMEM);
    k_cb_mma<<<BGR, 256, CBMMA_SMEM>>>(Cm, Bm);
    k_fused<<<BGR * 2, 256, FUSED_SMEM>>>(x, dt, dt_edge, dt_bias, Dv, masks, eidx, outp);
}